// round 16
// baseline (speedup 1.0000x reference)
#include <cuda_runtime.h>
#include <cstdint>
#include <cstddef>

// ---------------- problem constants ----------------
namespace {
constexpr int B    = 8;
constexpr int T    = 4096;
constexpr int NT   = B * T;        // 32768 tokens
constexpr int DIN  = 1176;
constexpr int D    = 1024;
constexpr int E    = 8;
constexpr int BNK  = 64;           // bottleneck
constexpr int L    = 4;
constexpr int OUTD = 4096;
constexpr int CAP  = 32768;        // max tokens per expert bucket
constexpr int TM   = 128;          // moe tokens per tile
constexpr int MOE_SMEM = 53248;    // H1s(34816) + W2s(18432); stage1 As+B1s alias inside
}

// ---------------- device scratch (no runtime allocs allowed) ----------------
__device__ float g_hA[(size_t)NT * D];
__device__ float g_hB[(size_t)NT * D];
__device__ float g_g[B * D];            // accumulated as SUM (atomic); skin scales 1/T + re-zeroes
__device__ float g_skin_probs[B * 3];
__device__ float g_skin_logits[B * 3];
__device__ int   g_counts[E];
__device__ int   g_btok[E * CAP];
__device__ float g_bw[E * CAP];
__device__ float g_aux_probs[B * E];
__device__ float g_aux_mask[B * E];
__device__ float g_aux_total;

// ---------------- precision helpers ----------------
__device__ __forceinline__ uint32_t f2tf(float x) {
  uint32_t r;
  asm("cvt.rna.tf32.f32 %0, %1;" : "=r"(r) : "f"(x));
  return r;
}

__device__ __forceinline__ uint4 f2tf4(float4 v) {
  return make_uint4(f2tf(v.x), f2tf(v.y), f2tf(v.z), f2tf(v.w));
}

// split two floats (x0=k, x1=k+1) into packed bf16x2 hi-pair and lo-pair
__device__ __forceinline__ void split2bf(float x0, float x1, uint32_t& hp, uint32_t& lp) {
  asm("cvt.rn.bf16x2.f32 %0, %1, %2;" : "=r"(hp) : "f"(x1), "f"(x0));  // hi half = x1
  float h0 = __uint_as_float(hp << 16);
  float h1 = __uint_as_float(hp & 0xFFFF0000u);
  float l0 = x0 - h0;
  float l1 = x1 - h1;
  asm("cvt.rn.bf16x2.f32 %0, %1, %2;" : "=r"(lp) : "f"(l1), "f"(l0));
}

// tf32 m16n8k8 mma (moe path)
__device__ __forceinline__ void mma8(float* c, const uint32_t* a, const uint32_t* b) {
  asm volatile(
      "mma.sync.aligned.m16n8k8.row.col.f32.tf32.tf32.f32 "
      "{%0,%1,%2,%3}, {%4,%5,%6,%7}, {%8,%9}, {%0,%1,%2,%3};"
      : "+f"(c[0]), "+f"(c[1]), "+f"(c[2]), "+f"(c[3])
      : "r"(a[0]), "r"(a[1]), "r"(a[2]), "r"(a[3]), "r"(b[0]), "r"(b[1]));
}

// bf16 m16n8k16 mma (in_proj path)
__device__ __forceinline__ void mma16bf(float* c, const uint32_t* a, const uint32_t* b) {
  asm volatile(
      "mma.sync.aligned.m16n8k16.row.col.f32.bf16.bf16.f32 "
      "{%0,%1,%2,%3}, {%4,%5,%6,%7}, {%8,%9}, {%0,%1,%2,%3};"
      : "+f"(c[0]), "+f"(c[1]), "+f"(c[2]), "+f"(c[3])
      : "r"(a[0]), "r"(a[1]), "r"(a[2]), "r"(a[3]), "r"(b[0]), "r"(b[1]));
}

// ---------------- in_proj GEMM (3-term split-BF16, k16 MMAs) + fused column-sum ----------------
// 128x128 tile, BK=16 (74 chunks, zero-padded tail), 256 threads, warp grid 2m x 4n.
// smem holds packed bf16 (hi,lo) k-pairs in separate planes: bytes == fp32 baseline.
__global__ __launch_bounds__(256) void inproj_mma(const float* __restrict__ X,
                                                  const float* __restrict__ W) {
  __shared__ uint32_t AsH[128][12];  // k-pair cols 0..7 used; (12r+c) bank bijection
  __shared__ uint32_t AsL[128][12];
  __shared__ uint32_t BsH[8][136];   // pair rows 0..7; (8p+n) bank bijection
  __shared__ uint32_t BsL[8][136];
  int tid = threadIdx.x, lane = tid & 31, wid = tid >> 5;
  int wm = (wid & 1) * 64, wn = (wid >> 1) * 32;
  int m0 = blockIdx.y * 128, n0 = blockIdx.x * 128;
  int ar = lane >> 2, ac = lane & 3;

  float acc[4][4][4];
#pragma unroll
  for (int i = 0; i < 4; i++)
#pragma unroll
    for (int j = 0; j < 4; j++)
#pragma unroll
      for (int q = 0; q < 4; q++) acc[i][j][q] = 0.f;

  // A loader: 128 rows x 2 thr, 8 floats each (la_k in {0,8})
  int la_m = tid >> 1, la_k = (tid & 1) * 8;
  // B loader: 8 k-pairs x 32 thr, 4 n-cols each (two gmem rows per pair)
  int lb_p = tid >> 5, lb_n = (tid & 31) * 4;
  const float* xptr = X + (size_t)(m0 + la_m) * DIN;
  const float* wptr = W + (size_t)n0 + lb_n;

  constexpr int NIT = (DIN + 15) / 16;  // 74
  const float4 z4 = make_float4(0.f, 0.f, 0.f, 0.f);

  float4 pa0, pa1, pb0, pb1;
  {
    bool okA = (la_k < DIN);
    pa0 = okA ? *(const float4*)(xptr + la_k)     : z4;
    pa1 = okA ? *(const float4*)(xptr + la_k + 4) : z4;
    bool okB = (2 * lb_p < DIN);
    pb0 = okB ? *(const float4*)(wptr + (size_t)(2 * lb_p) * D)     : z4;
    pb1 = okB ? *(const float4*)(wptr + (size_t)(2 * lb_p + 1) * D) : z4;
  }

  for (int it = 0; it < NIT; ++it) {
    __syncthreads();
    {
      // A: 8 floats -> 4 (hi,lo) pairs at cols (la_k>>1)+0..3
      uint32_t h0, l0, h1, l1, h2, l2, h3, l3;
      split2bf(pa0.x, pa0.y, h0, l0);
      split2bf(pa0.z, pa0.w, h1, l1);
      split2bf(pa1.x, pa1.y, h2, l2);
      split2bf(pa1.z, pa1.w, h3, l3);
      int cc = la_k >> 1;
      *(uint4*)&AsH[la_m][cc] = make_uint4(h0, h1, h2, h3);
      *(uint4*)&AsL[la_m][cc] = make_uint4(l0, l1, l2, l3);
      // B: pair rows (k0+2p, k0+2p+1), 4 n columns
      uint32_t bh0, bl0, bh1, bl1, bh2, bl2, bh3, bl3;
      split2bf(pb0.x, pb1.x, bh0, bl0);
      split2bf(pb0.y, pb1.y, bh1, bl1);
      split2bf(pb0.z, pb1.z, bh2, bl2);
      split2bf(pb0.w, pb1.w, bh3, bl3);
      *(uint4*)&BsH[lb_p][lb_n] = make_uint4(bh0, bh1, bh2, bh3);
      *(uint4*)&BsL[lb_p][lb_n] = make_uint4(bl0, bl1, bl2, bl3);
    }
    __syncthreads();
    if (it + 1 < NIT) {
      int k0 = (it + 1) * 16;
      bool okA = (k0 + la_k < DIN);
      pa0 = okA ? *(const float4*)(xptr + k0 + la_k)     : z4;
      pa1 = okA ? *(const float4*)(xptr + k0 + la_k + 4) : z4;
      bool okB = (k0 + 2 * lb_p < DIN);
      pb0 = okB ? *(const float4*)(wptr + (size_t)(k0 + 2 * lb_p) * D)     : z4;
      pb1 = okB ? *(const float4*)(wptr + (size_t)(k0 + 2 * lb_p + 1) * D) : z4;
    }
    // B fragments for all 4 j tiles
    uint32_t bh[4][2], bl[4][2];
#pragma unroll
    for (int j = 0; j < 4; j++) {
      int cb = wn + j * 8 + ar;
      bh[j][0] = BsH[ac][cb];
      bh[j][1] = BsH[ac + 4][cb];
      bl[j][0] = BsL[ac][cb];
      bl[j][1] = BsL[ac + 4][cb];
    }
#pragma unroll
    for (int i = 0; i < 4; i++) {
      int r0 = wm + i * 16 + ar;
      uint32_t ah[4], al[4];
      ah[0] = AsH[r0][ac];
      ah[1] = AsH[r0 + 8][ac];
      ah[2] = AsH[r0][ac + 4];
      ah[3] = AsH[r0 + 8][ac + 4];
      al[0] = AsL[r0][ac];
      al[1] = AsL[r0 + 8][ac];
      al[2] = AsL[r0][ac + 4];
      al[3] = AsL[r0 + 8][ac + 4];
#pragma unroll
      for (int j = 0; j < 4; j++) {
        mma16bf(acc[i][j], al, bh[j]);
        mma16bf(acc[i][j], ah, bl[j]);
        mma16bf(acc[i][j], ah, bh[j]);
      }
    }
  }
  int ac2 = (lane & 3) * 2;
#pragma unroll
  for (int i = 0; i < 4; i++) {
    int r = m0 + wm + i * 16 + ar;
#pragma unroll
    for (int j = 0; j < 4; j++) {
      int c = n0 + wn + j * 8 + ac2;
      *(float2*)&g_hA[(size_t)r * D + c]       = make_float2(acc[i][j][0], acc[i][j][1]);
      *(float2*)&g_hA[(size_t)(r + 8) * D + c] = make_float2(acc[i][j][2], acc[i][j][3]);
    }
  }

  // fused column-sum of this 128-row tile into g_g (rows all within one image)
  int img = blockIdx.y >> 5;
  float s[4][2];
#pragma unroll
  for (int j = 0; j < 4; j++) {
    s[j][0] = 0.f;
    s[j][1] = 0.f;
#pragma unroll
    for (int i = 0; i < 4; i++) {
      s[j][0] += acc[i][j][0] + acc[i][j][2];
      s[j][1] += acc[i][j][1] + acc[i][j][3];
    }
  }
#pragma unroll
  for (int j = 0; j < 4; j++) {
#pragma unroll
    for (int off = 4; off < 32; off <<= 1) {
      s[j][0] += __shfl_xor_sync(0xffffffffu, s[j][0], off);
      s[j][1] += __shfl_xor_sync(0xffffffffu, s[j][1], off);
    }
  }
  if (ar == 0) {
#pragma unroll
    for (int j = 0; j < 4; j++) {
      int c = n0 + wn + j * 8 + ac2;
      atomicAdd(&g_g[img * D + c],     s[j][0]);
      atomicAdd(&g_g[img * D + c + 1], s[j][1]);
    }
  }
}

// ---------------- skin classifier (reads g_g sums, scales 1/T; re-zeroes g_g; layer-0 prep) ----------------
__global__ __launch_bounds__(256) void skin_kernel(const float* __restrict__ w_sc1,
                                                   const float* __restrict__ b_sc1,
                                                   const float* __restrict__ w_sc2,
                                                   const float* __restrict__ b_sc2) {
  __shared__ float s1[B][64];
  __shared__ float lg[B][3];
  int tid = threadIdx.x;
  if (tid < E) g_counts[tid] = 0;
  if (tid < B * E) {
    g_aux_probs[tid] = 0.f;
    g_aux_mask[tid] = 0.f;
  }
  if (tid == 0) g_aux_total = 0.f;

  const float invT = 1.f / (float)T;
  for (int task = tid; task < B * 64; task += 256) {
    int img = task >> 6, j = task & 63;
    float a = b_sc1[j];
    const float* gr = g_g + img * D;
    for (int d = 0; d < D; d++) a = fmaf(gr[d] * invT, w_sc1[(size_t)d * 64 + j], a);
    s1[img][j] = fmaxf(a, 0.f);
  }
  __syncthreads();
  for (int i = tid; i < B * D; i += 256) g_g[i] = 0.f;

  if (tid < B * 3) {
    int img = tid / 3, c = tid % 3;
    float a = b_sc2[c];
    for (int k = 0; k < 64; k++) a = fmaf(s1[img][k], w_sc2[k * 3 + c], a);
    lg[img][c] = a;
    g_skin_logits[img * 3 + c] = a;
  }
  __syncthreads();
  if (tid < B) {
    float l0 = lg[tid][0], l1 = lg[tid][1], l2 = lg[tid][2];
    float m = fmaxf(l0, fmaxf(l1, l2));
    float p0 = expf(l0 - m), p1 = expf(l1 - m), p2 = expf(l2 - m);
    float inv = 1.f / (p0 + p1 + p2);
    g_skin_probs[tid * 3 + 0] = p0 * inv;
    g_skin_probs[tid * 3 + 1] = p1 * inv;
    g_skin_probs[tid * 3 + 2] = p2 * inv;
  }
}

// ---------------- per-layer prep (layers >= 1) ----------------
__global__ void prep_kernel() {
  int i = threadIdx.x;
  if (i < E) g_counts[i] = 0;
  if (i < B * E) {
    g_aux_probs[i] = 0.f;
    g_aux_mask[i] = 0.f;
  }
}

// ---------------- router v3 + parallel tail: 32 tokens/block, 4/warp; tail on lanes 0..3 ----------------
__global__ __launch_bounds__(256) void router_kernel(int flip,
                                                     const float* __restrict__ w_rimg_l,
                                                     const float* __restrict__ w_rskin_l) {
  __shared__ float ws[E][1028];
  const float* hcur = flip ? g_hB : g_hA;
  float* hnxt = flip ? g_hA : g_hB;
  int tid = threadIdx.x;

  for (int i = tid; i < D * E; i += 256) ws[i & 7][i >> 3] = w_rimg_l[i];
  __syncthreads();

  int wrp = tid >> 5, lane = tid & 31;
  int tbase = blockIdx.x * 32 + wrp * 4;

  float acc[4][E];
#pragma unroll
  for (int m = 0; m < 4; m++)
#pragma unroll
    for (int e = 0; e < E; e++) acc[m][e] = 0.f;

  const float* hbase = hcur + (size_t)tbase * D;
  float* obase = hnxt + (size_t)tbase * D;

#pragma unroll
  for (int k = 0; k < 8; k++) {
    int d = (k * 32 + lane) * 4;
    float4 hv[4];
#pragma unroll
    for (int m = 0; m < 4; m++) hv[m] = *(const float4*)(hbase + (size_t)m * D + d);
#pragma unroll
    for (int m = 0; m < 4; m++) *(float4*)(obase + (size_t)m * D + d) = hv[m];
#pragma unroll
    for (int e = 0; e < E; e++) {
      float4 wv = *(const float4*)&ws[e][d];
#pragma unroll
      for (int m = 0; m < 4; m++) {
        acc[m][e] = fmaf(hv[m].x, wv.x, acc[m][e]);
        acc[m][e] = fmaf(hv[m].y, wv.y, acc[m][e]);
        acc[m][e] = fmaf(hv[m].z, wv.z, acc[m][e]);
        acc[m][e] = fmaf(hv[m].w, wv.w, acc[m][e]);
      }
    }
  }
#pragma unroll
  for (int m = 0; m < 4; m++)
#pragma unroll
    for (int e = 0; e < E; e++)
#pragma unroll
      for (int off = 16; off > 0; off >>= 1)
        acc[m][e] += __shfl_xor_sync(0xffffffffu, acc[m][e], off);

  if (lane < 4) {
    int m = lane;
    int t = tbase + m;
    int img = t >> 12;
    float p[E];
    float mx = -1e30f;
#pragma unroll
    for (int e = 0; e < E; e++) {
      float s = acc[m][e];
#pragma unroll
      for (int k = 0; k < 3; k++) s = fmaf(g_skin_probs[img * 3 + k], w_rskin_l[k * E + e], s);
      p[e] = s;
      mx = fmaxf(mx, s);
    }
    float sum = 0.f;
#pragma unroll
    for (int e = 0; e < E; e++) {
      p[e] = expf(p[e] - mx);
      sum += p[e];
    }
    float inv = 1.f / sum;
#pragma unroll
    for (int e = 0; e < E; e++) p[e] *= inv;
    int i0 = 0;
#pragma unroll
    for (int e = 1; e < E; e++)
      if (p[e] > p[i0]) i0 = e;
    int i1 = (i0 == 0) ? 1 : 0;
#pragma unroll
    for (int e = 0; e < E; e++)
      if (e != i0 && p[e] > p[i1]) i1 = e;
    float denom = p[i0] + p[i1] + 1e-6f;
    float w0 = p[i0] / denom, w1 = p[i1] / denom;
    int pos0 = atomicAdd(&g_counts[i0], 1);
    g_btok[i0 * CAP + pos0] = t;
    g_bw[i0 * CAP + pos0] = w0;
    int pos1 = atomicAdd(&g_counts[i1], 1);
    g_btok[i1 * CAP + pos1] = t;
    g_bw[i1 * CAP + pos1] = w1;
#pragma unroll
    for (int e = 0; e < E; e++) atomicAdd(&g_aux_probs[img * E + e], p[e]);
    atomicAdd(&g_aux_mask[img * E + i0], 1.f);
    atomicAdd(&g_aux_mask[img * E + i1], 1.f);
  }
}

// ---------------- grouped MoE: plain TF32, M=128 token tile (warp 32x32), atomic scatter ----------------
__global__ __launch_bounds__(256) void moe_mma(int flip,
                                               const float* __restrict__ ew1_l,
                                               const float* __restrict__ eb1_l,
                                               const float* __restrict__ ew2_l,
                                               const float* __restrict__ eb2_l) {
  const float* hcur = flip ? g_hB : g_hA;
  float* hnxt = flip ? g_hA : g_hB;
  int tid = threadIdx.x, lane = tid & 31, wid = tid >> 5;

  // fused aux finalize (runs once per layer, after router)
  if (blockIdx.x == 0 && blockIdx.y == 0 && tid < 32) {
    float v0 = (g_aux_probs[tid] * (1.f / (float)T)) * (g_aux_mask[tid] * (1.f / (float)T));
    float v1 = (g_aux_probs[tid + 32] * (1.f / (float)T)) * (g_aux_mask[tid + 32] * (1.f / (float)T));
    float v = (v0 + v1) * (float)E;
#pragma unroll
    for (int off = 16; off > 0; off >>= 1) v += __shfl_xor_sync(0xffffffffu, v, off);
    if (tid == 0) g_aux_total += v;
  }

  int e = blockIdx.y;
  int n_e = g_counts[e];
  int t0 = blockIdx.x * TM;
  if (t0 >= n_e) return;
  int mrows = min(TM, n_e - t0);

  extern __shared__ __align__(16) char sbuf[];
  uint32_t* As  = (uint32_t*)sbuf;
  uint32_t* B1s = (uint32_t*)(sbuf + 18432);
  uint32_t* H1s = (uint32_t*)sbuf;
  uint32_t* W2s = (uint32_t*)(sbuf + 34816);
  __shared__ int   toks[TM];
  __shared__ float tws[TM];

  int wm = (wid & 3) * 32, wn = (wid >> 2) * 32;
  int ar = lane >> 2, ac = lane & 3;
  int c2 = (lane & 3) * 2;

  if (tid < TM) {
    int gi = t0 + tid;
    if (gi < n_e) {
      toks[tid] = g_btok[e * CAP + gi];
      tws[tid]  = g_bw[e * CAP + gi];
    } else {
      toks[tid] = 0;
      tws[tid]  = 0.f;
    }
  }
  __syncthreads();

  const float* w1e = ew1_l + (size_t)e * D * BNK;
  const float* w2e = ew2_l + (size_t)e * BNK * D;
  const float* b1e = eb1_l + (size_t)e * BNK;
  const float* b2e = eb2_l + (size_t)e * D;

  // ---- stage 1: H1 = relu(X(128x1024) @ W1(1024x64) + b1), BK=32 ----
  float acc1[2][4][4];
#pragma unroll
  for (int i = 0; i < 2; i++)
#pragma unroll
    for (int j = 0; j < 4; j++)
#pragma unroll
      for (int q = 0; q < 4; q++) acc1[i][j][q] = 0.f;

  int a_m = tid >> 1, a_k = (tid & 1) * 16;
  int b_k = tid >> 3, b_n = (tid & 7) * 8;
  const float* a_src = hcur + (size_t)toks[a_m] * D + a_k;

  float4 pa[4], pb[2];
#pragma unroll
  for (int q = 0; q < 4; q++) pa[q] = *(const float4*)(a_src + 4 * q);
  pb[0] = *(const float4*)(w1e + (size_t)b_k * BNK + b_n);
  pb[1] = *(const float4*)(w1e + (size_t)b_k * BNK + b_n + 4);

  for (int k0 = 0; k0 < D; k0 += 32) {
    __syncthreads();
#pragma unroll
    for (int q = 0; q < 4; q++) *(uint4*)&As[a_m * 36 + a_k + 4 * q] = f2tf4(pa[q]);
    *(uint4*)&B1s[b_k * 72 + b_n]     = f2tf4(pb[0]);
    *(uint4*)&B1s[b_k * 72 + b_n + 4] = f2tf4(pb[1]);
    __syncthreads();
    if (k0 + 32 < D) {
#pragma unroll
      for (int q = 0; q < 4; q++) pa[q] = *(const float4*)(a_src + k0 + 32 + 4 * q);
      pb[0] = *(const float4*)(w1e + (size_t)(k0 + 32 + b_k) * BNK + b_n);
      pb[1] = *(const float4*)(w1e + (size_t)(k0 + 32 + b_k) * BNK + b_n + 4);
    }
#pragma unroll
    for (int ks = 0; ks < 4; ks++) {
      int kb = ks * 8;
      int r0 = wm + ar;
      uint32_t a[2][4];
#pragma unroll
      for (int i = 0; i < 2; i++) {
        int rr = r0 + 16 * i;
        a[i][0] = As[rr * 36 + kb + ac];
        a[i][1] = As[(rr + 8) * 36 + kb + ac];
        a[i][2] = As[rr * 36 + kb + ac + 4];
        a[i][3] = As[(rr + 8) * 36 + kb + ac + 4];
      }
#pragma unroll
      for (int j = 0; j < 4; j++) {
        int cb = wn + j * 8 + ar;
        uint32_t b[2];
        b[0] = B1s[(kb + ac) * 72 + cb];
        b[1] = B1s[(kb + ac + 4) * 72 + cb];
        mma8(acc1[0][j], a[0], b);
        mma8(acc1[1][j], a[1], b);
      }
    }
  }
  __syncthreads();
  {
    int r = wm + ar;
#pragma unroll
    for (int i = 0; i < 2; i++) {
      int rr = r + 16 * i;
#pragma unroll
      for (int j = 0; j < 4; j++) {
        int c = wn + j * 8 + c2;
        H1s[rr * 68 + c]           = f2tf(fmaxf(acc1[i][j][0] + b1e[c], 0.f));
        H1s[rr * 68 + c + 1]       = f2tf(fmaxf(acc1[i][j][1] + b1e[c + 1], 0.f));
        H1s[(rr + 8) * 68 + c]     = f2tf(fmaxf(acc1[i][j][2] + b1e[c], 0.f));
        H1s[(rr + 8) * 68 + c + 1] = f2tf(fmaxf(acc1[i][j][3] + b1e[c + 1], 0.f));
      }
    }
  }

  // ---- stage 2: OUT = H1(128x64) @ W2(64x1024) + b2, c-chunk 64; atomic scatter ----
  int w_k = tid >> 2, w_n = (tid & 3) * 16;
  float4 pw[4];
#pragma unroll
  for (int q = 0; q < 4; q++)
    pw[q] = *(const float4*)(w2e + (size_t)w_k * D + w_n + 4 * q);

  for (int c0 = 0; c0 < D; c0 += 64) {
    __syncthreads();
#pragma unroll
    for (int q = 0; q < 4; q++) *(uint4*)&W2s[w_k * 72 + w_n + 4 * q] = f2tf4(pw[q]);
    __syncthreads();
    if (c0 + 64 < D) {
#pragma unroll
      for (int q = 0; q < 4; q++)
        pw[q] = *(const float4*)(w2e + (size_t)w_k * D + c0 + 64 + w_n + 4 * q);
    }
    float acc2[2][4][4];
#pragma unroll
    for (int i = 0; i < 2; i++)
#pragma unroll
      for (int j = 0; j < 4; j++)
#pragma unroll
        for (int q = 0; q < 4; q++) acc2[i][j][q] = 0.f;
#pragma unroll
    for (int ks = 0; ks < 8; ks++) {
      int kb = ks * 8;
      int r0 = wm + ar;
      uint32_t a[2][4];
#pragma unroll
      for (int i = 0; i < 2; i++) {
        int rr = r0 + 16 * i;
        a[i][0] = H1s[rr * 68 + kb + ac];
        a[i][1] = H1s[(rr + 8) * 68 + kb + ac];
        a[i][2] = H1s[rr * 68 + kb + ac + 4];
        a[i][3] = H1s[(rr + 8) * 68 + kb + ac + 4];
      }
#pragma unroll
      for (int j = 0; j < 4; j++) {
        int cb = wn + j * 8 + ar;
        uint32_t b[2];
        b[0] = W2s[(kb + ac) * 72 + cb];
        b[1] = W2s[(kb + ac + 4) * 72 + cb];
        mma8(acc2[0][j], a[0], b);
        mma8(acc2[1][j], a[1], b);
      }
    }
    int r = wm + ar;
#pragma unroll
    for (int i = 0; i < 2; i++) {
      int rr = r + 16 * i;
      if (rr < mrows) {
        float w = tws[rr];
        float* dst = hnxt + (size_t)toks[rr] * D + c0;
#pragma unroll
        for (int j = 0; j < 4; j++) {
          int c = wn + j * 8 + c2;
          atomicAdd(&dst[c],     w * (acc2[i][j][0] + b2e[c0 + c]));
          atomicAdd(&dst[c + 1], w * (acc2[i][j][1] + b2e[c0 + c + 1]));
        }
      }
      if (rr + 8 < mrows) {
        float w = tws[rr + 8];
        float* dst = hnxt + (size_t)toks[rr + 8] * D + c0;
#pragma unroll
        for (int j = 0; j < 4; j++) {
          int c = wn + j * 8 + c2;
          atomicAdd(&dst[c],     w * (acc2[i][j][2] + b2e[c0 + c]));
          atomicAdd(&dst[c + 1], w * (acc2[i][j][3] + b2e[c0 + c + 1]));
        }
      }
    }
  }
}

// ---------------- pooled = mean over T of final h (in g_hA after 4 layers) ----------------
__global__ void pooled_kernel(float* __restrict__ out) {
  int img = blockIdx.x;
  int d = blockIdx.y * 256 + threadIdx.x;
  const float* base = g_hA + (size_t)img * T * D + d;
  float s0 = 0.f, s1 = 0.f, s2 = 0.f, s3 = 0.f;
  for (int t = 0; t < T; t += 4) {
    s0 += base[(size_t)t * D];
    s1 += base[(size_t)(t + 1) * D];
    s2 += base[(size_t)(t + 2) * D];
    s3 += base[(size_t)(t + 3) * D];
  }
  out[img * D + d] = (s0 + s1 + s2 + s3) * (1.f / (float)T);
}

// ---------------- vision_proj = pooled @ w_out + b_out ----------------
__global__ __launch_bounds__(256) void vproj_kernel(const float* __restrict__ w_out,
                                                    const float* __restrict__ b_out,
                                                    float* __restrict__ out) {
  __shared__ float ps[B * D];
  for (int i = threadIdx.x; i < B * D; i += 256) ps[i] = out[i];
  __syncthreads();
  int o = blockIdx.x * 256 + threadIdx.x;
  float acc[B];
#pragma unroll
  for (int i = 0; i < B; i++) acc[i] = 0.f;
  for (int d = 0; d < D; d++) {
    float wv = w_out[(size_t)d * OUTD + o];
#pragma unroll
    for (int i = 0; i < B; i++) acc[i] = fmaf(ps[i * D + d], wv, acc[i]);
  }
  float bo = b_out[o];
  float* vp = out + B * D;
#pragma unroll
  for (int i = 0; i < B; i++) vp[(size_t)i * OUTD + o] = acc[i] + bo;
}

// ---------------- pack tail outputs ----------------
__global__ void pack_kernel(float* __restrict__ out, int out_size) {
  const int base = B * D + B * OUTD;
  int i = threadIdx.x;
  if (i == 0) out[base] = g_aux_total;
  if (i < B * 3) out[base + 1 + i] = g_skin_logits[i];
  for (int j = base + 1 + B * 3 + i; j < out_size; j += 256) out[j] = 0.f;
}

// ---------------- launch ----------------
extern "C" void kernel_launch(void* const* d_in, const int* in_sizes, int n_in,
                              void* d_out, int out_size) {
  const float* pixel_values = (const float*)d_in[0];
  const float* w_in    = (const float*)d_in[2];
  const float* w_sc1   = (const float*)d_in[3];
  const float* b_sc1   = (const float*)d_in[4];
  const float* w_sc2   = (const float*)d_in[5];
  const float* b_sc2   = (const float*)d_in[6];
  const float* w_rimg  = (const float*)d_in[7];
  const float* w_rskin = (const float*)d_in[8];
  const float* ew1     = (const float*)d_in[9];
  const float* eb1     = (const float*)d_in[10];
  const float* ew2     = (const float*)d_in[11];
  const float* eb2     = (const float*)d_in[12];
  const float* w_out   = (const float*)d_in[13];
  const float* b_out   = (const float*)d_in[14];
  float* out = (float*)d_out;

  cudaFuncSetAttribute(moe_mma, cudaFuncAttributeMaxDynamicSharedMemorySize, MOE_SMEM);

  inproj_mma<<<dim3(D / 128, NT / 128), 256>>>(pixel_values, w_in);
  skin_kernel<<<1, 256>>>(w_sc1, b_sc1, w_sc2, b_sc2);

  for (int l = 0; l < L; l++) {
    int flip = l & 1;
    if (l > 0) prep_kernel<<<1, 64>>>();
    router_kernel<<<NT / 32, 256>>>(flip, w_rimg + (size_t)l * D * E, w_rskin + (size_t)l * 3 * E);
    moe_mma<<<dim3(NT / TM, E), 256, MOE_SMEM>>>(flip,
                                                 ew1 + (size_t)l * E * D * BNK,
                                                 eb1 + (size_t)l * E * BNK,
                                                 ew2 + (size_t)l * E * BNK * D,
                                                 eb2 + (size_t)l * E * D);
  }

  pooled_kernel<<<dim3(B, D / 256), 256>>>(out);
  vproj_kernel<<<OUTD / 256, 256>>>(w_out, b_out, out);
  pack_kernel<<<1, 256>>>(out, out_size);
}

// round 17
// speedup vs baseline: 1.0088x; 1.0088x over previous
#include <cuda_runtime.h>
#include <cstdint>
#include <cstddef>

// ---------------- problem constants ----------------
namespace {
constexpr int B    = 8;
constexpr int T    = 4096;
constexpr int NT   = B * T;        // 32768 tokens
constexpr int DIN  = 1176;
constexpr int D    = 1024;
constexpr int E    = 8;
constexpr int BNK  = 64;           // bottleneck
constexpr int L    = 4;
constexpr int OUTD = 4096;
constexpr int CAP  = 32768;        // max tokens per expert bucket
constexpr int TM   = 128;          // moe tokens per tile
constexpr int MOE_SMEM = 53248;    // H1s(34816) + W2s(18432); stage1 As+B1s alias inside
}

// ---------------- device scratch (no runtime allocs allowed) ----------------
__device__ float g_hA[(size_t)NT * D];
__device__ float g_hB[(size_t)NT * D];
__device__ float g_g[B * D];            // accumulated as SUM (atomic); skin scales 1/T + re-zeroes
__device__ float g_skin_probs[B * 3];
__device__ float g_skin_logits[B * 3];
__device__ int   g_counts[E];
__device__ int   g_btok[E * CAP];
__device__ float g_bw[E * CAP];
__device__ float g_aux_probs[B * E];
__device__ float g_aux_mask[B * E];
__device__ float g_aux_total;

// ---------------- precision helpers ----------------
__device__ __forceinline__ uint32_t f2tf(float x) {
  uint32_t r;
  asm("cvt.rna.tf32.f32 %0, %1;" : "=r"(r) : "f"(x));
  return r;
}

__device__ __forceinline__ uint4 f2tf4(float4 v) {
  return make_uint4(f2tf(v.x), f2tf(v.y), f2tf(v.z), f2tf(v.w));
}

// split two floats (x0=k, x1=k+1) into packed bf16x2 hi-pair and lo-pair
__device__ __forceinline__ void split2bf(float x0, float x1, uint32_t& hp, uint32_t& lp) {
  asm("cvt.rn.bf16x2.f32 %0, %1, %2;" : "=r"(hp) : "f"(x1), "f"(x0));  // hi half = x1
  float h0 = __uint_as_float(hp << 16);
  float h1 = __uint_as_float(hp & 0xFFFF0000u);
  float l0 = x0 - h0;
  float l1 = x1 - h1;
  asm("cvt.rn.bf16x2.f32 %0, %1, %2;" : "=r"(lp) : "f"(l1), "f"(l0));
}

// tf32 m16n8k8 mma (moe path)
__device__ __forceinline__ void mma8(float* c, const uint32_t* a, const uint32_t* b) {
  asm volatile(
      "mma.sync.aligned.m16n8k8.row.col.f32.tf32.tf32.f32 "
      "{%0,%1,%2,%3}, {%4,%5,%6,%7}, {%8,%9}, {%0,%1,%2,%3};"
      : "+f"(c[0]), "+f"(c[1]), "+f"(c[2]), "+f"(c[3])
      : "r"(a[0]), "r"(a[1]), "r"(a[2]), "r"(a[3]), "r"(b[0]), "r"(b[1]));
}

// bf16 m16n8k16 mma (in_proj path)
__device__ __forceinline__ void mma16bf(float* c, const uint32_t* a, const uint32_t* b) {
  asm volatile(
      "mma.sync.aligned.m16n8k16.row.col.f32.bf16.bf16.f32 "
      "{%0,%1,%2,%3}, {%4,%5,%6,%7}, {%8,%9}, {%0,%1,%2,%3};"
      : "+f"(c[0]), "+f"(c[1]), "+f"(c[2]), "+f"(c[3])
      : "r"(a[0]), "r"(a[1]), "r"(a[2]), "r"(a[3]), "r"(b[0]), "r"(b[1]));
}

// ---------------- in_proj GEMM (3-term split-BF16, k16 MMAs) + fused column-sum ----------------
// 128x128 tile, BK=16 (74 chunks, zero-padded tail), 256 threads, warp grid 2m x 4n.
// smem holds packed bf16 (hi,lo) k-pairs in separate planes: bytes == fp32 baseline.
__global__ __launch_bounds__(256) void inproj_mma(const float* __restrict__ X,
                                                  const float* __restrict__ W) {
  __shared__ uint32_t AsH[128][12];  // k-pair cols 0..7 used; (12r+c) bank bijection
  __shared__ uint32_t AsL[128][12];
  __shared__ uint32_t BsH[8][136];   // pair rows 0..7; (8p+n) bank bijection
  __shared__ uint32_t BsL[8][136];
  int tid = threadIdx.x, lane = tid & 31, wid = tid >> 5;
  int wm = (wid & 1) * 64, wn = (wid >> 1) * 32;
  int m0 = blockIdx.y * 128, n0 = blockIdx.x * 128;
  int ar = lane >> 2, ac = lane & 3;

  float acc[4][4][4];
#pragma unroll
  for (int i = 0; i < 4; i++)
#pragma unroll
    for (int j = 0; j < 4; j++)
#pragma unroll
      for (int q = 0; q < 4; q++) acc[i][j][q] = 0.f;

  // A loader: 128 rows x 2 thr, 8 floats each (la_k in {0,8})
  int la_m = tid >> 1, la_k = (tid & 1) * 8;
  // B loader: 8 k-pairs x 32 thr, 4 n-cols each (two gmem rows per pair)
  int lb_p = tid >> 5, lb_n = (tid & 31) * 4;
  const float* xptr = X + (size_t)(m0 + la_m) * DIN;
  const float* wptr = W + (size_t)n0 + lb_n;

  constexpr int NIT = (DIN + 15) / 16;  // 74
  const float4 z4 = make_float4(0.f, 0.f, 0.f, 0.f);

  float4 pa0, pa1, pb0, pb1;
  {
    bool okA = (la_k < DIN);
    pa0 = okA ? *(const float4*)(xptr + la_k)     : z4;
    pa1 = okA ? *(const float4*)(xptr + la_k + 4) : z4;
    bool okB = (2 * lb_p < DIN);
    pb0 = okB ? *(const float4*)(wptr + (size_t)(2 * lb_p) * D)     : z4;
    pb1 = okB ? *(const float4*)(wptr + (size_t)(2 * lb_p + 1) * D) : z4;
  }

  for (int it = 0; it < NIT; ++it) {
    __syncthreads();
    {
      // A: 8 floats -> 4 (hi,lo) pairs at cols (la_k>>1)+0..3
      uint32_t h0, l0, h1, l1, h2, l2, h3, l3;
      split2bf(pa0.x, pa0.y, h0, l0);
      split2bf(pa0.z, pa0.w, h1, l1);
      split2bf(pa1.x, pa1.y, h2, l2);
      split2bf(pa1.z, pa1.w, h3, l3);
      int cc = la_k >> 1;
      *(uint4*)&AsH[la_m][cc] = make_uint4(h0, h1, h2, h3);
      *(uint4*)&AsL[la_m][cc] = make_uint4(l0, l1, l2, l3);
      // B: pair rows (k0+2p, k0+2p+1), 4 n columns
      uint32_t bh0, bl0, bh1, bl1, bh2, bl2, bh3, bl3;
      split2bf(pb0.x, pb1.x, bh0, bl0);
      split2bf(pb0.y, pb1.y, bh1, bl1);
      split2bf(pb0.z, pb1.z, bh2, bl2);
      split2bf(pb0.w, pb1.w, bh3, bl3);
      *(uint4*)&BsH[lb_p][lb_n] = make_uint4(bh0, bh1, bh2, bh3);
      *(uint4*)&BsL[lb_p][lb_n] = make_uint4(bl0, bl1, bl2, bl3);
    }
    __syncthreads();
    if (it + 1 < NIT) {
      int k0 = (it + 1) * 16;
      bool okA = (k0 + la_k < DIN);
      pa0 = okA ? *(const float4*)(xptr + k0 + la_k)     : z4;
      pa1 = okA ? *(const float4*)(xptr + k0 + la_k + 4) : z4;
      bool okB = (k0 + 2 * lb_p < DIN);
      pb0 = okB ? *(const float4*)(wptr + (size_t)(k0 + 2 * lb_p) * D)     : z4;
      pb1 = okB ? *(const float4*)(wptr + (size_t)(k0 + 2 * lb_p + 1) * D) : z4;
    }
    // B fragments for all 4 j tiles
    uint32_t bh[4][2], bl[4][2];
#pragma unroll
    for (int j = 0; j < 4; j++) {
      int cb = wn + j * 8 + ar;
      bh[j][0] = BsH[ac][cb];
      bh[j][1] = BsH[ac + 4][cb];
      bl[j][0] = BsL[ac][cb];
      bl[j][1] = BsL[ac + 4][cb];
    }
#pragma unroll
    for (int i = 0; i < 4; i++) {
      int r0 = wm + i * 16 + ar;
      uint32_t ah[4], al[4];
      ah[0] = AsH[r0][ac];
      ah[1] = AsH[r0 + 8][ac];
      ah[2] = AsH[r0][ac + 4];
      ah[3] = AsH[r0 + 8][ac + 4];
      al[0] = AsL[r0][ac];
      al[1] = AsL[r0 + 8][ac];
      al[2] = AsL[r0][ac + 4];
      al[3] = AsL[r0 + 8][ac + 4];
#pragma unroll
      for (int j = 0; j < 4; j++) {
        mma16bf(acc[i][j], al, bh[j]);
        mma16bf(acc[i][j], ah, bl[j]);
        mma16bf(acc[i][j], ah, bh[j]);
      }
    }
  }
  int ac2 = (lane & 3) * 2;
#pragma unroll
  for (int i = 0; i < 4; i++) {
    int r = m0 + wm + i * 16 + ar;
#pragma unroll
    for (int j = 0; j < 4; j++) {
      int c = n0 + wn + j * 8 + ac2;
      *(float2*)&g_hA[(size_t)r * D + c]       = make_float2(acc[i][j][0], acc[i][j][1]);
      *(float2*)&g_hA[(size_t)(r + 8) * D + c] = make_float2(acc[i][j][2], acc[i][j][3]);
    }
  }

  // fused column-sum of this 128-row tile into g_g (rows all within one image)
  int img = blockIdx.y >> 5;
  float s[4][2];
#pragma unroll
  for (int j = 0; j < 4; j++) {
    s[j][0] = 0.f;
    s[j][1] = 0.f;
#pragma unroll
    for (int i = 0; i < 4; i++) {
      s[j][0] += acc[i][j][0] + acc[i][j][2];
      s[j][1] += acc[i][j][1] + acc[i][j][3];
    }
  }
#pragma unroll
  for (int j = 0; j < 4; j++) {
#pragma unroll
    for (int off = 4; off < 32; off <<= 1) {
      s[j][0] += __shfl_xor_sync(0xffffffffu, s[j][0], off);
      s[j][1] += __shfl_xor_sync(0xffffffffu, s[j][1], off);
    }
  }
  if (ar == 0) {
#pragma unroll
    for (int j = 0; j < 4; j++) {
      int c = n0 + wn + j * 8 + ac2;
      atomicAdd(&g_g[img * D + c],     s[j][0]);
      atomicAdd(&g_g[img * D + c + 1], s[j][1]);
    }
  }
}

// ---------------- skin classifier (reads g_g sums, scales 1/T; re-zeroes g_g; layer-0 prep) ----------------
__global__ __launch_bounds__(256) void skin_kernel(const float* __restrict__ w_sc1,
                                                   const float* __restrict__ b_sc1,
                                                   const float* __restrict__ w_sc2,
                                                   const float* __restrict__ b_sc2) {
  __shared__ float s1[B][64];
  __shared__ float lg[B][3];
  int tid = threadIdx.x;
  if (tid < E) g_counts[tid] = 0;
  if (tid < B * E) {
    g_aux_probs[tid] = 0.f;
    g_aux_mask[tid] = 0.f;
  }
  if (tid == 0) g_aux_total = 0.f;

  const float invT = 1.f / (float)T;
  for (int task = tid; task < B * 64; task += 256) {
    int img = task >> 6, j = task & 63;
    float a = b_sc1[j];
    const float* gr = g_g + img * D;
    for (int d = 0; d < D; d++) a = fmaf(gr[d] * invT, w_sc1[(size_t)d * 64 + j], a);
    s1[img][j] = fmaxf(a, 0.f);
  }
  __syncthreads();
  for (int i = tid; i < B * D; i += 256) g_g[i] = 0.f;

  if (tid < B * 3) {
    int img = tid / 3, c = tid % 3;
    float a = b_sc2[c];
    for (int k = 0; k < 64; k++) a = fmaf(s1[img][k], w_sc2[k * 3 + c], a);
    lg[img][c] = a;
    g_skin_logits[img * 3 + c] = a;
  }
  __syncthreads();
  if (tid < B) {
    float l0 = lg[tid][0], l1 = lg[tid][1], l2 = lg[tid][2];
    float m = fmaxf(l0, fmaxf(l1, l2));
    float p0 = expf(l0 - m), p1 = expf(l1 - m), p2 = expf(l2 - m);
    float inv = 1.f / (p0 + p1 + p2);
    g_skin_probs[tid * 3 + 0] = p0 * inv;
    g_skin_probs[tid * 3 + 1] = p1 * inv;
    g_skin_probs[tid * 3 + 2] = p2 * inv;
  }
}

// ---------------- per-layer prep (layers >= 1) ----------------
__global__ void prep_kernel() {
  int i = threadIdx.x;
  if (i < E) g_counts[i] = 0;
  if (i < B * E) {
    g_aux_probs[i] = 0.f;
    g_aux_mask[i] = 0.f;
  }
}

// ---------------- router v3 + parallel tail: 32 tokens/block, 4/warp; tail on lanes 0..3 ----------------
__global__ __launch_bounds__(256) void router_kernel(int flip,
                                                     const float* __restrict__ w_rimg_l,
                                                     const float* __restrict__ w_rskin_l) {
  __shared__ float ws[E][1028];
  const float* hcur = flip ? g_hB : g_hA;
  float* hnxt = flip ? g_hA : g_hB;
  int tid = threadIdx.x;

  for (int i = tid; i < D * E; i += 256) ws[i & 7][i >> 3] = w_rimg_l[i];
  __syncthreads();

  int wrp = tid >> 5, lane = tid & 31;
  int tbase = blockIdx.x * 32 + wrp * 4;

  float acc[4][E];
#pragma unroll
  for (int m = 0; m < 4; m++)
#pragma unroll
    for (int e = 0; e < E; e++) acc[m][e] = 0.f;

  const float* hbase = hcur + (size_t)tbase * D;
  float* obase = hnxt + (size_t)tbase * D;

#pragma unroll
  for (int k = 0; k < 8; k++) {
    int d = (k * 32 + lane) * 4;
    float4 hv[4];
#pragma unroll
    for (int m = 0; m < 4; m++) hv[m] = *(const float4*)(hbase + (size_t)m * D + d);
#pragma unroll
    for (int m = 0; m < 4; m++) *(float4*)(obase + (size_t)m * D + d) = hv[m];
#pragma unroll
    for (int e = 0; e < E; e++) {
      float4 wv = *(const float4*)&ws[e][d];
#pragma unroll
      for (int m = 0; m < 4; m++) {
        acc[m][e] = fmaf(hv[m].x, wv.x, acc[m][e]);
        acc[m][e] = fmaf(hv[m].y, wv.y, acc[m][e]);
        acc[m][e] = fmaf(hv[m].z, wv.z, acc[m][e]);
        acc[m][e] = fmaf(hv[m].w, wv.w, acc[m][e]);
      }
    }
  }
#pragma unroll
  for (int m = 0; m < 4; m++)
#pragma unroll
    for (int e = 0; e < E; e++)
#pragma unroll
      for (int off = 16; off > 0; off >>= 1)
        acc[m][e] += __shfl_xor_sync(0xffffffffu, acc[m][e], off);

  if (lane < 4) {
    int m = lane;
    int t = tbase + m;
    int img = t >> 12;
    float p[E];
    float mx = -1e30f;
#pragma unroll
    for (int e = 0; e < E; e++) {
      float s = acc[m][e];
#pragma unroll
      for (int k = 0; k < 3; k++) s = fmaf(g_skin_probs[img * 3 + k], w_rskin_l[k * E + e], s);
      p[e] = s;
      mx = fmaxf(mx, s);
    }
    float sum = 0.f;
#pragma unroll
    for (int e = 0; e < E; e++) {
      p[e] = expf(p[e] - mx);
      sum += p[e];
    }
    float inv = 1.f / sum;
#pragma unroll
    for (int e = 0; e < E; e++) p[e] *= inv;
    int i0 = 0;
#pragma unroll
    for (int e = 1; e < E; e++)
      if (p[e] > p[i0]) i0 = e;
    int i1 = (i0 == 0) ? 1 : 0;
#pragma unroll
    for (int e = 0; e < E; e++)
      if (e != i0 && p[e] > p[i1]) i1 = e;
    float denom = p[i0] + p[i1] + 1e-6f;
    float w0 = p[i0] / denom, w1 = p[i1] / denom;
    int pos0 = atomicAdd(&g_counts[i0], 1);
    g_btok[i0 * CAP + pos0] = t;
    g_bw[i0 * CAP + pos0] = w0;
    int pos1 = atomicAdd(&g_counts[i1], 1);
    g_btok[i1 * CAP + pos1] = t;
    g_bw[i1 * CAP + pos1] = w1;
#pragma unroll
    for (int e = 0; e < E; e++) atomicAdd(&g_aux_probs[img * E + e], p[e]);
    atomicAdd(&g_aux_mask[img * E + i0], 1.f);
    atomicAdd(&g_aux_mask[img * E + i1], 1.f);
  }
}

// ---------------- grouped MoE: plain TF32, M=128 token tile (warp 32x32), atomic scatter ----------------
__global__ __launch_bounds__(256) void moe_mma(int flip,
                                               const float* __restrict__ ew1_l,
                                               const float* __restrict__ eb1_l,
                                               const float* __restrict__ ew2_l,
                                               const float* __restrict__ eb2_l) {
  const float* hcur = flip ? g_hB : g_hA;
  float* hnxt = flip ? g_hA : g_hB;
  int tid = threadIdx.x, lane = tid & 31, wid = tid >> 5;

  // fused aux finalize (runs once per layer, after router)
  if (blockIdx.x == 0 && blockIdx.y == 0 && tid < 32) {
    float v0 = (g_aux_probs[tid] * (1.f / (float)T)) * (g_aux_mask[tid] * (1.f / (float)T));
    float v1 = (g_aux_probs[tid + 32] * (1.f / (float)T)) * (g_aux_mask[tid + 32] * (1.f / (float)T));
    float v = (v0 + v1) * (float)E;
#pragma unroll
    for (int off = 16; off > 0; off >>= 1) v += __shfl_xor_sync(0xffffffffu, v, off);
    if (tid == 0) g_aux_total += v;
  }

  int e = blockIdx.y;
  int n_e = g_counts[e];
  int t0 = blockIdx.x * TM;
  if (t0 >= n_e) return;
  int mrows = min(TM, n_e - t0);

  extern __shared__ __align__(16) char sbuf[];
  uint32_t* As  = (uint32_t*)sbuf;
  uint32_t* B1s = (uint32_t*)(sbuf + 18432);
  uint32_t* H1s = (uint32_t*)sbuf;
  uint32_t* W2s = (uint32_t*)(sbuf + 34816);
  __shared__ int   toks[TM];
  __shared__ float tws[TM];

  int wm = (wid & 3) * 32, wn = (wid >> 2) * 32;
  int ar = lane >> 2, ac = lane & 3;
  int c2 = (lane & 3) * 2;

  if (tid < TM) {
    int gi = t0 + tid;
    if (gi < n_e) {
      toks[tid] = g_btok[e * CAP + gi];
      tws[tid]  = g_bw[e * CAP + gi];
    } else {
      toks[tid] = 0;
      tws[tid]  = 0.f;
    }
  }
  __syncthreads();

  const float* w1e = ew1_l + (size_t)e * D * BNK;
  const float* w2e = ew2_l + (size_t)e * BNK * D;
  const float* b1e = eb1_l + (size_t)e * BNK;
  const float* b2e = eb2_l + (size_t)e * D;

  // ---- stage 1: H1 = relu(X(128x1024) @ W1(1024x64) + b1), BK=32 ----
  float acc1[2][4][4];
#pragma unroll
  for (int i = 0; i < 2; i++)
#pragma unroll
    for (int j = 0; j < 4; j++)
#pragma unroll
      for (int q = 0; q < 4; q++) acc1[i][j][q] = 0.f;

  int a_m = tid >> 1, a_k = (tid & 1) * 16;
  int b_k = tid >> 3, b_n = (tid & 7) * 8;
  const float* a_src = hcur + (size_t)toks[a_m] * D + a_k;

  float4 pa[4], pb[2];
#pragma unroll
  for (int q = 0; q < 4; q++) pa[q] = *(const float4*)(a_src + 4 * q);
  pb[0] = *(const float4*)(w1e + (size_t)b_k * BNK + b_n);
  pb[1] = *(const float4*)(w1e + (size_t)b_k * BNK + b_n + 4);

  for (int k0 = 0; k0 < D; k0 += 32) {
    __syncthreads();
#pragma unroll
    for (int q = 0; q < 4; q++) *(uint4*)&As[a_m * 36 + a_k + 4 * q] = f2tf4(pa[q]);
    *(uint4*)&B1s[b_k * 72 + b_n]     = f2tf4(pb[0]);
    *(uint4*)&B1s[b_k * 72 + b_n + 4] = f2tf4(pb[1]);
    __syncthreads();
    if (k0 + 32 < D) {
#pragma unroll
      for (int q = 0; q < 4; q++) pa[q] = *(const float4*)(a_src + k0 + 32 + 4 * q);
      pb[0] = *(const float4*)(w1e + (size_t)(k0 + 32 + b_k) * BNK + b_n);
      pb[1] = *(const float4*)(w1e + (size_t)(k0 + 32 + b_k) * BNK + b_n + 4);
    }
#pragma unroll
    for (int ks = 0; ks < 4; ks++) {
      int kb = ks * 8;
      int r0 = wm + ar;
      uint32_t a[2][4];
#pragma unroll
      for (int i = 0; i < 2; i++) {
        int rr = r0 + 16 * i;
        a[i][0] = As[rr * 36 + kb + ac];
        a[i][1] = As[(rr + 8) * 36 + kb + ac];
        a[i][2] = As[rr * 36 + kb + ac + 4];
        a[i][3] = As[(rr + 8) * 36 + kb + ac + 4];
      }
#pragma unroll
      for (int j = 0; j < 4; j++) {
        int cb = wn + j * 8 + ar;
        uint32_t b[2];
        b[0] = B1s[(kb + ac) * 72 + cb];
        b[1] = B1s[(kb + ac + 4) * 72 + cb];
        mma8(acc1[0][j], a[0], b);
        mma8(acc1[1][j], a[1], b);
      }
    }
  }
  __syncthreads();
  {
    int r = wm + ar;
#pragma unroll
    for (int i = 0; i < 2; i++) {
      int rr = r + 16 * i;
#pragma unroll
      for (int j = 0; j < 4; j++) {
        int c = wn + j * 8 + c2;
        H1s[rr * 68 + c]           = f2tf(fmaxf(acc1[i][j][0] + b1e[c], 0.f));
        H1s[rr * 68 + c + 1]       = f2tf(fmaxf(acc1[i][j][1] + b1e[c + 1], 0.f));
        H1s[(rr + 8) * 68 + c]     = f2tf(fmaxf(acc1[i][j][2] + b1e[c], 0.f));
        H1s[(rr + 8) * 68 + c + 1] = f2tf(fmaxf(acc1[i][j][3] + b1e[c + 1], 0.f));
      }
    }
  }

  // ---- stage 2: OUT = H1(128x64) @ W2(64x1024) + b2, c-chunk 64; atomic scatter ----
  int w_k = tid >> 2, w_n = (tid & 3) * 16;
  float4 pw[4];
#pragma unroll
  for (int q = 0; q < 4; q++)
    pw[q] = *(const float4*)(w2e + (size_t)w_k * D + w_n + 4 * q);

  for (int c0 = 0; c0 < D; c0 += 64) {
    __syncthreads();
#pragma unroll
    for (int q = 0; q < 4; q++) *(uint4*)&W2s[w_k * 72 + w_n + 4 * q] = f2tf4(pw[q]);
    __syncthreads();
    if (c0 + 64 < D) {
#pragma unroll
      for (int q = 0; q < 4; q++)
        pw[q] = *(const float4*)(w2e + (size_t)w_k * D + c0 + 64 + w_n + 4 * q);
    }
    float acc2[2][4][4];
#pragma unroll
    for (int i = 0; i < 2; i++)
#pragma unroll
      for (int j = 0; j < 4; j++)
#pragma unroll
        for (int q = 0; q < 4; q++) acc2[i][j][q] = 0.f;
#pragma unroll
    for (int ks = 0; ks < 8; ks++) {
      int kb = ks * 8;
      int r0 = wm + ar;
      uint32_t a[2][4];
#pragma unroll
      for (int i = 0; i < 2; i++) {
        int rr = r0 + 16 * i;
        a[i][0] = H1s[rr * 68 + kb + ac];
        a[i][1] = H1s[(rr + 8) * 68 + kb + ac];
        a[i][2] = H1s[rr * 68 + kb + ac + 4];
        a[i][3] = H1s[(rr + 8) * 68 + kb + ac + 4];
      }
#pragma unroll
      for (int j = 0; j < 4; j++) {
        int cb = wn + j * 8 + ar;
        uint32_t b[2];
        b[0] = W2s[(kb + ac) * 72 + cb];
        b[1] = W2s[(kb + ac + 4) * 72 + cb];
        mma8(acc2[0][j], a[0], b);
        mma8(acc2[1][j], a[1], b);
      }
    }
    int r = wm + ar;
#pragma unroll
    for (int i = 0; i < 2; i++) {
      int rr = r + 16 * i;
      if (rr < mrows) {
        float w = tws[rr];
        float* dst = hnxt + (size_t)toks[rr] * D + c0;
#pragma unroll
        for (int j = 0; j < 4; j++) {
          int c = wn + j * 8 + c2;
          atomicAdd(&dst[c],     w * (acc2[i][j][0] + b2e[c0 + c]));
          atomicAdd(&dst[c + 1], w * (acc2[i][j][1] + b2e[c0 + c + 1]));
        }
      }
      if (rr + 8 < mrows) {
        float w = tws[rr + 8];
        float* dst = hnxt + (size_t)toks[rr + 8] * D + c0;
#pragma unroll
        for (int j = 0; j < 4; j++) {
          int c = wn + j * 8 + c2;
          atomicAdd(&dst[c],     w * (acc2[i][j][2] + b2e[c0 + c]));
          atomicAdd(&dst[c + 1], w * (acc2[i][j][3] + b2e[c0 + c + 1]));
        }
      }
    }
  }
}

// ---------------- pooled = mean over T of final h (in g_hA after 4 layers) ----------------
__global__ void pooled_kernel(float* __restrict__ out) {
  int img = blockIdx.x;
  int d = blockIdx.y * 256 + threadIdx.x;
  const float* base = g_hA + (size_t)img * T * D + d;
  float s0 = 0.f, s1 = 0.f, s2 = 0.f, s3 = 0.f;
  for (int t = 0; t < T; t += 4) {
    s0 += base[(size_t)t * D];
    s1 += base[(size_t)(t + 1) * D];
    s2 += base[(size_t)(t + 2) * D];
    s3 += base[(size_t)(t + 3) * D];
  }
  out[img * D + d] = (s0 + s1 + s2 + s3) * (1.f / (float)T);
}

// ---------------- vision_proj = pooled @ w_out + b_out ----------------
__global__ __launch_bounds__(256) void vproj_kernel(const float* __restrict__ w_out,
                                                    const float* __restrict__ b_out,
                                                    float* __restrict__ out) {
  __shared__ float ps[B * D];
  for (int i = threadIdx.x; i < B * D; i += 256) ps[i] = out[i];
  __syncthreads();
  int o = blockIdx.x * 256 + threadIdx.x;
  float acc[B];
#pragma unroll
  for (int i = 0; i < B; i++) acc[i] = 0.f;
  for (int d = 0; d < D; d++) {
    float wv = w_out[(size_t)d * OUTD + o];
#pragma unroll
    for (int i = 0; i < B; i++) acc[i] = fmaf(ps[i * D + d], wv, acc[i]);
  }
  float bo = b_out[o];
  float* vp = out + B * D;
#pragma unroll
  for (int i = 0; i < B; i++) vp[(size_t)i * OUTD + o] = acc[i] + bo;
}

// ---------------- pack tail outputs ----------------
__global__ void pack_kernel(float* __restrict__ out, int out_size) {
  const int base = B * D + B * OUTD;
  int i = threadIdx.x;
  if (i == 0) out[base] = g_aux_total;
  if (i < B * 3) out[base + 1 + i] = g_skin_logits[i];
  for (int j = base + 1 + B * 3 + i; j < out_size; j += 256) out[j] = 0.f;
}

// ---------------- launch ----------------
extern "C" void kernel_launch(void* const* d_in, const int* in_sizes, int n_in,
                              void* d_out, int out_size) {
  const float* pixel_values = (const float*)d_in[0];
  const float* w_in    = (const float*)d_in[2];
  const float* w_sc1   = (const float*)d_in[3];
  const float* b_sc1   = (const float*)d_in[4];
  const float* w_sc2   = (const float*)d_in[5];
  const float* b_sc2   = (const float*)d_in[6];
  const float* w_rimg  = (const float*)d_in[7];
  const float* w_rskin = (const float*)d_in[8];
  const float* ew1     = (const float*)d_in[9];
  const float* eb1     = (const float*)d_in[10];
  const float* ew2     = (const float*)d_in[11];
  const float* eb2     = (const float*)d_in[12];
  const float* w_out   = (const float*)d_in[13];
  const float* b_out   = (const float*)d_in[14];
  float* out = (float*)d_out;

  cudaFuncSetAttribute(moe_mma, cudaFuncAttributeMaxDynamicSharedMemorySize, MOE_SMEM);

  inproj_mma<<<dim3(D / 128, NT / 128), 256>>>(pixel_values, w_in);
  skin_kernel<<<1, 256>>>(w_sc1, b_sc1, w_sc2, b_sc2);

  for (int l = 0; l < L; l++) {
    int flip = l & 1;
    if (l > 0) prep_kernel<<<1, 64>>>();
    router_kernel<<<NT / 32, 256>>>(flip, w_rimg + (size_t)l * D * E, w_rskin + (size_t)l * 3 * E);
    moe_mma<<<dim3(NT / TM, E), 256, MOE_SMEM>>>(flip,
                                                 ew1 + (size_t)l * E * D * BNK,
                                                 eb1 + (size_t)l * E * BNK,
                                                 ew2 + (size_t)l * E * BNK * D,
                                                 eb2 + (size_t)l * E * D);
  }

  pooled_kernel<<<dim3(B, D / 256), 256>>>(out);
  vproj_kernel<<<OUTD / 256, 256>>>(w_out, b_out, out);
  pack_kernel<<<1, 256>>>(out, out_size);
}